// round 1
// baseline (speedup 1.0000x reference)
#include <cuda_runtime.h>
#include <math.h>

// ---------------- constants ----------------
static constexpr int   T      = 300;
static constexpr int   KSRM   = 77;   // alpha kernel taps (tau=10, eps=0.01)
static constexpr int   KREF   = 11;   // refractory taps (tau=1, mult=-20)
static constexpr float THETA  = 10.0f;

// ---------------- device-global scratch (no allocation allowed) ----------------
__device__ float g_SRM[KSRM];
__device__ float g_REF[KREF];
__device__ float g_bufY[39321600];   // max: u1/s1 = 8*16*32*32*300
__device__ float g_bufX[9830400];    // max: 8*16*16*16*300

// ---------------- filter init (double precision to match numpy, cast to f32) ----------------
__global__ void init_filters() {
    int i = threadIdx.x;
    if (i < KSRM) {
        double v = (double)i / 10.0 * exp(1.0 - (double)i / 10.0);
        g_SRM[i] = (float)v;
    }
    if (i < KREF) {
        double v = -20.0 * (double)i * exp(1.0 - (double)i);
        g_REF[i] = (float)v;
    }
}

// ---------------- causal FIR along T (psp) ----------------
__global__ void psp_kernel(const float* __restrict__ in, float* __restrict__ out, int total) {
    int idx = blockIdx.x * blockDim.x + threadIdx.x;
    if (idx >= total) return;
    int t   = idx % T;
    int row = idx / T;
    const float* p = in + (size_t)row * T;
    float acc = 0.f;
    int kmax = min(KSRM - 1, t);
    // SRM[0] == 0 exactly, skip it
    #pragma unroll 4
    for (int s = 1; s <= kmax; s++)
        acc = fmaf(g_SRM[s], p[t - s], acc);
    out[idx] = acc;
}

// ---------------- spatial conv per timestep ----------------
// grid: x = t-tiles, y = Wout, z = (n*Cout + o)*Hout + h
__global__ void conv_kernel(const float* __restrict__ in, const float* __restrict__ wgt,
                            float* __restrict__ out,
                            int Cin, int Hin, int Win,
                            int Cout, int Hout, int Wout,
                            int Kh, int Kw, int pad) {
    extern __shared__ float sw[];
    int w  = blockIdx.y;
    int z  = blockIdx.z;
    int h  = z % Hout;
    int no = z / Hout;
    int o  = no % Cout;
    int n  = no / Cout;
    int nw = Cin * Kh * Kw;
    for (int i = threadIdx.x; i < nw; i += blockDim.x)
        sw[i] = wgt[(size_t)o * nw + i];
    __syncthreads();
    int t = blockIdx.x * blockDim.x + threadIdx.x;
    if (t >= T) return;

    float acc = 0.f;
    for (int c = 0; c < Cin; c++) {
        const float* inc = in + ((size_t)(n * Cin + c) * Hin) * Win * T;
        for (int kh = 0; kh < Kh; kh++) {
            int ih = h + kh - pad;
            if (ih < 0 || ih >= Hin) continue;
            for (int kw = 0; kw < Kw; kw++) {
                int iw = w + kw - pad;
                if (iw < 0 || iw >= Win) continue;
                acc = fmaf(sw[(c * Kh + kh) * Kw + kw],
                           inc[((size_t)ih * Win + iw) * T + t], acc);
            }
        }
    }
    out[((size_t)z * Wout + w) * T + t] = acc;
}

// ---------------- LIF spike generation with refractory feedback (in-place) ----------------
__global__ void spike_kernel(float* u, int M) {
    int m = blockIdx.x * blockDim.x + threadIdx.x;
    if (m >= M) return;
    float ref[KREF];
    float buf[KREF];
    #pragma unroll
    for (int k = 0; k < KREF; k++) { ref[k] = g_REF[k]; buf[k] = 0.f; }
    float* p = u + (size_t)m * T;
    for (int t = 0; t < T; t++) {
        float ueff = p[t] + buf[0];
        float s = (ueff >= THETA) ? 1.f : 0.f;
        if (s != 0.f) {
            #pragma unroll
            for (int k = 1; k < KREF; k++) buf[k] += ref[k];  // REF[0] == 0
        }
        #pragma unroll
        for (int k = 0; k < KREF - 1; k++) buf[k] = buf[k + 1];
        buf[KREF - 1] = 0.f;
        p[t] = s;
    }
}

// ---------------- 2x2 sum pool * 2.75 ----------------
__global__ void pool_kernel(const float* __restrict__ in, float* __restrict__ out,
                            int Ho, int Wo, int totalOut) {
    int idx = blockIdx.x * blockDim.x + threadIdx.x;
    if (idx >= totalOut) return;
    int t = idx % T; int r = idx / T;
    int w = r % Wo; r /= Wo;
    int h = r % Ho; r /= Ho;           // r = n*C + c
    int Wi = Wo * 2;
    size_t base = (((size_t)r * (Ho * 2) + h * 2) * Wi + w * 2) * T + t;
    float a = in[base];
    float b = in[base + T];
    float c = in[base + (size_t)Wi * T];
    float d = in[base + (size_t)Wi * T + T];
    out[idx] = 2.75f * ((a + b) + (c + d));
}

// ---------------- dense: (N,64,8,8,T) x (10,64,8,8) -> (N,10,T) ----------------
__global__ void dense_kernel(const float* __restrict__ in, const float* __restrict__ wfc,
                             float* __restrict__ out, int totalOut) {
    int idx = blockIdx.x * blockDim.x + threadIdx.x;
    if (idx >= totalOut) return;    // totalOut = 8*10*300
    int t = idx % T; int r = idx / T;
    int o = r % 10;  int n = r / 10;
    const float* pin = in + (size_t)n * 4096 * T + t;
    const float* pw  = wfc + o * 4096;
    float acc = 0.f;
    #pragma unroll 8
    for (int i = 0; i < 4096; i++)
        acc = fmaf(pw[i], pin[(size_t)i * T], acc);
    out[idx] = acc;
}

// ---------------- launch ----------------
extern "C" void kernel_launch(void* const* d_in, const int* in_sizes, int n_in,
                              void* d_out, int out_size) {
    const float* x   = (const float*)d_in[0];   // (8,2,34,34,300)
    const float* w1  = (const float*)d_in[1];   // (16,2,5,5,1)
    const float* w2  = (const float*)d_in[2];   // (32,16,3,3,1)
    const float* w3  = (const float*)d_in[3];   // (64,32,3,3,1)
    const float* wfc = (const float*)d_in[4];   // (10,64,8,8)
    float* out = (float*)d_out;                 // (8,10,1,1,300) = 24000

    void *pY = nullptr, *pX = nullptr;
    cudaGetSymbolAddress(&pY, g_bufY);
    cudaGetSymbolAddress(&pX, g_bufX);
    float* Y = (float*)pY;
    float* X = (float*)pX;

    init_filters<<<1, 128>>>();

    const int tBlocks = (T + 127) / 128;  // 3

    // ---- layer 1: s1 = spike(conv5x5(psp(x))) ----
    {
        int total = 8 * 2 * 34 * 34 * T;                       // 5,548,800
        psp_kernel<<<(total + 255) / 256, 256>>>(x, X, total);
        conv_kernel<<<dim3(tBlocks, 32, 8 * 16 * 32), 128, 2 * 5 * 5 * sizeof(float)>>>(
            X, w1, Y, 2, 34, 34, 16, 32, 32, 5, 5, 1);
        spike_kernel<<<(131072 + 255) / 256, 256>>>(Y, 8 * 16 * 32 * 32);
    }
    // ---- layer 2: s2 = spike(psp(pool2(s1)))  [pool/psp commuted] ----
    {
        int total = 8 * 16 * 16 * 16 * T;                      // 9,830,400
        pool_kernel<<<(total + 255) / 256, 256>>>(Y, X, 16, 16, total);
        psp_kernel<<<(total + 255) / 256, 256>>>(X, Y, total);
        spike_kernel<<<(32768 + 255) / 256, 256>>>(Y, 8 * 16 * 16 * 16);
    }
    // ---- layer 3: s3 = spike(conv3x3(psp(s2))) ----
    {
        int total = 8 * 16 * 16 * 16 * T;
        psp_kernel<<<(total + 255) / 256, 256>>>(Y, X, total);
        conv_kernel<<<dim3(tBlocks, 16, 8 * 32 * 16), 128, 16 * 3 * 3 * sizeof(float)>>>(
            X, w2, Y, 16, 16, 16, 32, 16, 16, 3, 3, 1);
        spike_kernel<<<(65536 + 255) / 256, 256>>>(Y, 8 * 32 * 16 * 16);
    }
    // ---- layer 4: s4 = spike(psp(pool2(s3))) ----
    {
        int total = 8 * 32 * 8 * 8 * T;                        // 4,915,200
        pool_kernel<<<(total + 255) / 256, 256>>>(Y, X, 8, 8, total);
        psp_kernel<<<(total + 255) / 256, 256>>>(X, Y, total);
        spike_kernel<<<(16384 + 255) / 256, 256>>>(Y, 8 * 32 * 8 * 8);
    }
    // ---- layer 5: s5 = spike(conv3x3(psp(s4))) ----
    {
        int total = 8 * 32 * 8 * 8 * T;
        psp_kernel<<<(total + 255) / 256, 256>>>(Y, X, total);
        conv_kernel<<<dim3(tBlocks, 8, 8 * 64 * 8), 128, 32 * 3 * 3 * sizeof(float)>>>(
            X, w3, Y, 32, 8, 8, 64, 8, 8, 3, 3, 1);
        spike_kernel<<<(32768 + 255) / 256, 256>>>(Y, 8 * 64 * 8 * 8);
    }
    // ---- output layer: spike(dense(psp(s5))) ----
    {
        int total = 8 * 64 * 8 * 8 * T;                        // 9,830,400
        psp_kernel<<<(total + 255) / 256, 256>>>(Y, X, total);
        int totalFc = 8 * 10 * T;                              // 24,000
        dense_kernel<<<(totalFc + 255) / 256, 256>>>(X, wfc, out, totalFc);
        spike_kernel<<<1, 128>>>(out, 8 * 10);
    }
}

// round 2
// speedup vs baseline: 3.0831x; 3.0831x over previous
#include <cuda_runtime.h>
#include <math.h>

static constexpr int   T     = 300;
static constexpr int   KSRM  = 77;
static constexpr int   KREF  = 11;
static constexpr int   JT    = 10;   // psp outputs per thread (T % JT == 0)

// ---------------- device-global scratch ----------------
__device__ float g_SRM[KSRM];
__device__ float g_REF[KREF];
__device__ float g_bufY[39321600];   // 131072*300
__device__ float g_bufX[9830400];
__device__ float g_bufZ[9830400];

// ---------------- filter init (double, matches numpy) ----------------
__global__ void init_filters() {
    int i = threadIdx.x;
    if (i < KSRM) g_SRM[i] = (float)((double)i / 10.0 * exp(1.0 - (double)i / 10.0));
    if (i < KREF) g_REF[i] = (float)(-20.0 * (double)i * exp(1.0 - (double)i));
}

// ---------------- transpose (R,C) -> (C,R), for input (M0,T) -> (T,M0) ----------------
__global__ void transpose_k(const float* __restrict__ in, float* __restrict__ out,
                            int R, int C) {
    __shared__ float tile[32][33];
    int cb = blockIdx.x * 32, rb = blockIdx.y * 32;
    #pragma unroll
    for (int j = 0; j < 32; j += 8) {
        int r = rb + threadIdx.y + j, c = cb + threadIdx.x;
        tile[threadIdx.y + j][threadIdx.x] = (r < R && c < C) ? in[(size_t)r * C + c] : 0.f;
    }
    __syncthreads();
    #pragma unroll
    for (int j = 0; j < 32; j += 8) {
        int r = rb + threadIdx.x, c = cb + threadIdx.y + j;
        if (c < C && r < R) out[(size_t)c * R + r] = tile[threadIdx.x][threadIdx.y + j];
    }
}

// ---------------- psp: causal 77-tap FIR, time-major, 10 outputs/thread ----------------
// in/out layout: (T, M). Each thread: column m, outputs t0..t0+9.
__global__ void psp_tm(const float* __restrict__ in, float* __restrict__ out, int M) {
    __shared__ float ssrm[KSRM];
    for (int i = threadIdx.x; i < KSRM; i += blockDim.x) ssrm[i] = g_SRM[i];
    __syncthreads();

    int m  = blockIdx.x * blockDim.x + threadIdx.x;
    int t0 = blockIdx.y * JT;
    bool valid = (m < M);

    float acc[JT];
    float xv[JT];
    #pragma unroll
    for (int j = 0; j < JT; j++) acc[j] = 0.f;
    // window for s=1: xv[j] = x[t0 + j - 1]
    #pragma unroll
    for (int j = 0; j < JT; j++) {
        int ti = t0 + j - 1;
        xv[j] = (valid && ti >= 0) ? in[(size_t)ti * M + m] : 0.f;
    }
    #pragma unroll
    for (int s = 1; s <= KSRM - 1; s++) {
        float wt = ssrm[s];
        #pragma unroll
        for (int j = 0; j < JT; j++) acc[j] = fmaf(wt, xv[j], acc[j]);
        if (s < KSRM - 1) {
            #pragma unroll
            for (int k = JT - 1; k > 0; k--) xv[k] = xv[k - 1];
            int ti = t0 - s - 1;
            xv[0] = (valid && ti >= 0) ? in[(size_t)ti * M + m] : 0.f;
        }
    }
    if (valid) {
        #pragma unroll
        for (int j = 0; j < JT; j++) out[(size_t)(t0 + j) * M + m] = acc[j];
    }
}

// ---------------- conv, time-major, 8 output channels per thread ----------------
// grid: (Hout/HT, N*(Cout/8), T), block: Wout*HT
__global__ void conv_tm(const float* __restrict__ in, const float* __restrict__ wgt,
                        float* __restrict__ out,
                        int Cin, int Hin, int Win,
                        int Cout, int Hout, int Wout,
                        int K, int pad, int N, int HT,
                        int Min, int Mout) {
    extern __shared__ float sw[];  // 8 * Cin*K*K
    int t  = blockIdx.z;
    int og = blockIdx.y % (Cout / 8);
    int n  = blockIdx.y / (Cout / 8);
    int nw = Cin * K * K;
    for (int i = threadIdx.x; i < 8 * nw; i += blockDim.x)
        sw[i] = wgt[(size_t)(og * 8) * nw + i];
    __syncthreads();

    int w = threadIdx.x % Wout;
    int h = blockIdx.x * HT + threadIdx.x / Wout;
    if (h >= Hout) return;

    float acc[8];
    #pragma unroll
    for (int o = 0; o < 8; o++) acc[o] = 0.f;

    const float* inb = in + (size_t)t * Min + (size_t)n * Cin * Hin * Win;
    for (int c = 0; c < Cin; c++) {
        for (int kh = 0; kh < K; kh++) {
            int ih = h + kh - pad;
            if (ih < 0 || ih >= Hin) continue;
            for (int kw = 0; kw < K; kw++) {
                int iw = w + kw - pad;
                if (iw < 0 || iw >= Win) continue;
                float v = inb[((size_t)c * Hin + ih) * Win + iw];
                int wi = (c * K + kh) * K + kw;
                #pragma unroll
                for (int o = 0; o < 8; o++)
                    acc[o] = fmaf(sw[o * nw + wi], v, acc[o]);
            }
        }
    }
    size_t ob = (size_t)t * Mout + ((size_t)(n * Cout + og * 8) * Hout + h) * Wout + w;
    size_t cs = (size_t)Hout * Wout;
    #pragma unroll
    for (int o = 0; o < 8; o++) out[ob + o * cs] = acc[o];
}

// ---------------- spike scan, time-major, in-place ----------------
__global__ void spike_tm(float* __restrict__ u, int M) {
    int m = blockIdx.x * blockDim.x + threadIdx.x;
    if (m >= M) return;
    float ref[KREF], buf[KREF];
    #pragma unroll
    for (int k = 0; k < KREF; k++) { ref[k] = g_REF[k]; buf[k] = 0.f; }
    for (int t = 0; t < T; t++) {
        float ueff = u[(size_t)t * M + m] + buf[0];
        float s = (ueff >= 10.0f) ? 1.0f : 0.0f;
        if (s != 0.f) {
            #pragma unroll
            for (int k = 1; k < KREF; k++) buf[k] += ref[k];   // REF[0]==0
        }
        #pragma unroll
        for (int k = 0; k < KREF - 1; k++) buf[k] = buf[k + 1];
        buf[KREF - 1] = 0.f;
        u[(size_t)t * M + m] = s;
    }
}

// ---------------- 2x2 sum pool * 2.75, time-major ----------------
__global__ void pool_tm(const float* __restrict__ in, float* __restrict__ out,
                        int Mi, int Mo, int Hi, int Wi, int total) {
    int idx = blockIdx.x * blockDim.x + threadIdx.x;
    if (idx >= total) return;
    int m = idx % Mo, t = idx / Mo;
    int Wo = Wi >> 1, Ho = Hi >> 1;
    int w = m % Wo; int tmp = m / Wo;
    int h = tmp % Ho; int nc = tmp / Ho;
    const float* p = in + (size_t)t * Mi + ((size_t)nc * Hi + 2 * h) * Wi + 2 * w;
    out[idx] = 2.75f * ((p[0] + p[1]) + (p[Wi] + p[Wi + 1]));
}

// ---------------- dense: warp per output, time-major in -> (t,80) out ----------------
__global__ void dense_tm(const float* __restrict__ in, const float* __restrict__ wfc,
                         float* __restrict__ out) {
    int gw   = (blockIdx.x * blockDim.x + threadIdx.x) >> 5;
    int lane = threadIdx.x & 31;
    if (gw >= T * 80) return;
    int t = gw / 80, r = gw % 80;
    int n = r / 10, o = r % 10;
    const float* pin = in + (size_t)t * 32768 + n * 4096;
    const float* pw  = wfc + o * 4096;
    float acc = 0.f;
    #pragma unroll 4
    for (int i = lane; i < 4096; i += 32) acc = fmaf(pw[i], pin[i], acc);
    #pragma unroll
    for (int off = 16; off; off >>= 1) acc += __shfl_down_sync(0xffffffffu, acc, off);
    if (lane == 0) out[(size_t)t * 80 + r] = acc;
}

// ---------------- final spike scan, time-major in -> T-minor d_out ----------------
__global__ void spike_tm_out(const float* __restrict__ u, float* __restrict__ out, int M) {
    int m = blockIdx.x * blockDim.x + threadIdx.x;
    if (m >= M) return;
    float ref[KREF], buf[KREF];
    #pragma unroll
    for (int k = 0; k < KREF; k++) { ref[k] = g_REF[k]; buf[k] = 0.f; }
    for (int t = 0; t < T; t++) {
        float ueff = u[(size_t)t * M + m] + buf[0];
        float s = (ueff >= 10.0f) ? 1.0f : 0.0f;
        if (s != 0.f) {
            #pragma unroll
            for (int k = 1; k < KREF; k++) buf[k] += ref[k];
        }
        #pragma unroll
        for (int k = 0; k < KREF - 1; k++) buf[k] = buf[k + 1];
        buf[KREF - 1] = 0.f;
        out[(size_t)m * T + t] = s;
    }
}

// ---------------- launch ----------------
extern "C" void kernel_launch(void* const* d_in, const int* in_sizes, int n_in,
                              void* d_out, int out_size) {
    const float* x   = (const float*)d_in[0];
    const float* w1  = (const float*)d_in[1];
    const float* w2  = (const float*)d_in[2];
    const float* w3  = (const float*)d_in[3];
    const float* wfc = (const float*)d_in[4];
    float* out = (float*)d_out;

    void *pY, *pX, *pZ;
    cudaGetSymbolAddress(&pY, g_bufY);
    cudaGetSymbolAddress(&pX, g_bufX);
    cudaGetSymbolAddress(&pZ, g_bufZ);
    float* Y = (float*)pY;
    float* X = (float*)pX;
    float* Z = (float*)pZ;

    init_filters<<<1, 128>>>();

    auto pspGrid = [](int M) { return dim3((M + 255) / 256, T / JT, 1); };

    // ---- input transpose: (18496, 300) -> (300, 18496) ----
    transpose_k<<<dim3((T + 31) / 32, (18496 + 31) / 32), dim3(32, 8)>>>(x, Z, 18496, T);

    // ---- layer 1: s1 = spike(conv5x5(psp(x))) ----
    psp_tm<<<pspGrid(18496), 256>>>(Z, X, 18496);
    conv_tm<<<dim3(4, 16, T), 256, 8 * 50 * sizeof(float)>>>(
        X, w1, Y, 2, 34, 34, 16, 32, 32, 5, 1, 8, 8, 18496, 131072);
    spike_tm<<<(131072 + 255) / 256, 256>>>(Y, 131072);

    // ---- layer 2: s2 = spike(psp(pool2(s1))) ----
    {
        int total = T * 32768;
        pool_tm<<<(total + 255) / 256, 256>>>(Y, X, 131072, 32768, 32, 32, total);
        psp_tm<<<pspGrid(32768), 256>>>(X, Z, 32768);
        spike_tm<<<(32768 + 255) / 256, 256>>>(Z, 32768);
    }
    // ---- layer 3: s3 = spike(conv3x3(psp(s2))) ----
    psp_tm<<<pspGrid(32768), 256>>>(Z, X, 32768);
    conv_tm<<<dim3(1, 32, T), 256, 8 * 144 * sizeof(float)>>>(
        X, w2, Y, 16, 16, 16, 32, 16, 16, 3, 1, 8, 16, 32768, 65536);
    spike_tm<<<(65536 + 255) / 256, 256>>>(Y, 65536);

    // ---- layer 4: s4 = spike(psp(pool2(s3))) ----
    {
        int total = T * 16384;
        pool_tm<<<(total + 255) / 256, 256>>>(Y, X, 65536, 16384, 16, 16, total);
        psp_tm<<<pspGrid(16384), 256>>>(X, Z, 16384);
        spike_tm<<<(16384 + 255) / 256, 256>>>(Z, 16384);
    }
    // ---- layer 5: s5 = spike(conv3x3(psp(s4))) ----
    psp_tm<<<pspGrid(16384), 256>>>(Z, X, 16384);
    conv_tm<<<dim3(1, 64, T), 64, 8 * 288 * sizeof(float)>>>(
        X, w3, Y, 32, 8, 8, 64, 8, 8, 3, 1, 8, 8, 16384, 32768);
    spike_tm<<<(32768 + 255) / 256, 256>>>(Y, 32768);

    // ---- output: spike(dense(psp(s5))) ----
    psp_tm<<<pspGrid(32768), 256>>>(Y, X, 32768);
    dense_tm<<<(T * 80 * 32 + 255) / 256, 256>>>(X, wfc, Z);
    spike_tm_out<<<1, 128>>>(Z, out, 80);
}

// round 3
// speedup vs baseline: 5.7437x; 1.8629x over previous
#include <cuda_runtime.h>
#include <math.h>

static constexpr int T    = 300;
static constexpr int KSRM = 77;
static constexpr int KREF = 11;
static constexpr int JT   = 10;

// ---------------- device-global scratch ----------------
__device__ float g_SRM[KSRM];
__device__ float g_REF[KREF];
__device__ float g_bufY[39321600];   // 131072*300
__device__ float g_bufX[9830400];
__device__ float g_bufZ[9830400];

__global__ void init_filters() {
    int i = threadIdx.x;
    if (i < KSRM) g_SRM[i] = (float)((double)i / 10.0 * exp(1.0 - (double)i / 10.0));
    if (i < KREF) g_REF[i] = (float)(-20.0 * (double)i * exp(1.0 - (double)i));
}

// ---------------- transpose (R,C) -> (C,R) ----------------
__global__ void transpose_k(const float* __restrict__ in, float* __restrict__ out,
                            int R, int C) {
    __shared__ float tile[32][33];
    int cb = blockIdx.x * 32, rb = blockIdx.y * 32;
    #pragma unroll
    for (int j = 0; j < 32; j += 8) {
        int r = rb + threadIdx.y + j, c = cb + threadIdx.x;
        tile[threadIdx.y + j][threadIdx.x] = (r < R && c < C) ? in[(size_t)r * C + c] : 0.f;
    }
    __syncthreads();
    #pragma unroll
    for (int j = 0; j < 32; j += 8) {
        int r = rb + threadIdx.x, c = cb + threadIdx.y + j;
        if (c < C && r < R) out[(size_t)c * R + r] = tile[threadIdx.x][threadIdx.y + j];
    }
}

// ---------------- psp: 77-tap causal FIR, circular register window ----------------
// layout (T, M). Thread: column m, outputs t0..t0+JT-1. INTERIOR: no t<0 predicates.
template<bool INTERIOR>
__global__ void psp_t(const float* __restrict__ in, float* __restrict__ out,
                      int M, int ybase) {
    __shared__ float ssrm[KSRM];
    for (int i = threadIdx.x; i < KSRM; i += blockDim.x) ssrm[i] = g_SRM[i];
    __syncthreads();

    int m = blockIdx.x * blockDim.x + threadIdx.x;
    if (m >= M) return;
    int t0 = (blockIdx.y + ybase) * JT;
    const float* pm = in + m;

    float acc[JT];
    float xv[JT];
    #pragma unroll
    for (int j = 0; j < JT; j++) acc[j] = 0.f;
    // initial window: x[t0+j-1] stored at slot (t0+j-1) mod JT == (j-1) mod JT
    #pragma unroll
    for (int j = 0; j < JT; j++) {
        int ti = t0 + j - 1;
        int slot = ((j - 1) % JT + JT) % JT;
        xv[slot] = (INTERIOR || ti >= 0) ? __ldg(&pm[(size_t)ti * M]) : 0.f;
    }
    #pragma unroll
    for (int s = 1; s < KSRM; s++) {
        float wt = ssrm[s];
        #pragma unroll
        for (int j = 0; j < JT; j++) {
            int slot = (((j - s) % JT) + JT) % JT;
            acc[j] = fmaf(wt, xv[slot], acc[j]);
        }
        if (s < KSRM - 1) {
            int ti = t0 - s - 1;
            int slot = (((-s - 1) % JT) + JT) % JT;
            xv[slot] = (INTERIOR || ti >= 0) ? __ldg(&pm[(size_t)ti * M]) : 0.f;
        }
    }
    #pragma unroll
    for (int j = 0; j < JT; j++) out[(size_t)(t0 + j) * M + m] = acc[j];
}

// ---------------- templated conv, time-major, smem input tile ----------------
// block: x = (WOUT/WV)*HOUT position-threads, y = OBLK/OV o-slices
// grid:  x = COUT/OBLK, y = N, z = T
template<int CIN, int K, int PAD, int HIN, int WIN, int HOUT, int WOUT,
         int COUT, int OBLK, int OV, int WV>
__global__ void conv_t(const float* __restrict__ in, const float* __restrict__ wgt,
                       float* __restrict__ out, int Min, int Mout) {
    constexpr int CKK  = CIN * K * K;
    constexpr int WTHR = WOUT / WV;
    constexpr int TILE = CIN * HIN * WIN;
    __shared__ float s_in[TILE];

    int t = blockIdx.z, n = blockIdx.y;
    const float* inb = in + (size_t)t * Min + (size_t)n * TILE;
    int nth = blockDim.x * blockDim.y;
    int tid = threadIdx.y * blockDim.x + threadIdx.x;
    for (int i = tid; i < TILE; i += nth) s_in[i] = inb[i];
    __syncthreads();

    int w0 = (threadIdx.x % WTHR) * WV;
    int h  = threadIdx.x / WTHR;
    int o0 = blockIdx.x * OBLK + threadIdx.y * OV;

    float acc[OV][WV];
    #pragma unroll
    for (int o = 0; o < OV; o++)
        #pragma unroll
        for (int v = 0; v < WV; v++) acc[o][v] = 0.f;

    const float* wp = wgt + (size_t)o0 * CKK;

    #pragma unroll 4
    for (int c = 0; c < CIN; c++) {
        #pragma unroll
        for (int kh = 0; kh < K; kh++) {
            int ih = h + kh - PAD;
            bool okh = (ih >= 0 && ih < HIN);
            float win[WV + K - 1];
            #pragma unroll
            for (int j = 0; j < WV + K - 1; j++) {
                int iw = w0 + j - PAD;
                win[j] = (okh && iw >= 0 && iw < WIN)
                       ? s_in[(c * HIN + ih) * WIN + iw] : 0.f;
            }
            #pragma unroll
            for (int kw = 0; kw < K; kw++) {
                #pragma unroll
                for (int o = 0; o < OV; o++) {
                    float wv = __ldg(&wp[o * CKK + (c * K + kh) * K + kw]);
                    #pragma unroll
                    for (int v = 0; v < WV; v++)
                        acc[o][v] = fmaf(wv, win[kw + v], acc[o][v]);
                }
            }
        }
    }
    size_t ob = (size_t)t * Mout + (((size_t)n * COUT + o0) * HOUT + h) * WOUT + w0;
    #pragma unroll
    for (int o = 0; o < OV; o++)
        #pragma unroll
        for (int v = 0; v < WV; v++)
            out[ob + (size_t)o * (HOUT * WOUT) + v] = acc[o][v];
}

// ---------------- spike scan, time-major, in-place ----------------
__global__ void spike_tm(float* __restrict__ u, int M) {
    int m = blockIdx.x * blockDim.x + threadIdx.x;
    if (m >= M) return;
    float ref[KREF], buf[KREF];
    #pragma unroll
    for (int k = 0; k < KREF; k++) { ref[k] = g_REF[k]; buf[k] = 0.f; }
    for (int t = 0; t < T; t++) {
        float ueff = u[(size_t)t * M + m] + buf[0];
        float s = (ueff >= 10.0f) ? 1.0f : 0.0f;
        if (s != 0.f) {
            #pragma unroll
            for (int k = 1; k < KREF; k++) buf[k] += ref[k];
        }
        #pragma unroll
        for (int k = 0; k < KREF - 1; k++) buf[k] = buf[k + 1];
        buf[KREF - 1] = 0.f;
        u[(size_t)t * M + m] = s;
    }
}

// ---------------- 2x2 sum pool * 2.75, time-major ----------------
__global__ void pool_tm(const float* __restrict__ in, float* __restrict__ out,
                        int Mi, int Mo, int Hi, int Wi, int total) {
    int idx = blockIdx.x * blockDim.x + threadIdx.x;
    if (idx >= total) return;
    int m = idx % Mo, t = idx / Mo;
    int Wo = Wi >> 1, Ho = Hi >> 1;
    int w = m % Wo; int tmp = m / Wo;
    int h = tmp % Ho; int nc = tmp / Ho;
    const float* p = in + (size_t)t * Mi + ((size_t)nc * Hi + 2 * h) * Wi + 2 * w;
    out[idx] = 2.75f * ((p[0] + p[1]) + (p[Wi] + p[Wi + 1]));
}

// ---------------- dense: block per (n,t), smem activation tile, warp per output ----------------
__global__ void dense_t(const float* __restrict__ in, const float* __restrict__ wfc,
                        float* __restrict__ out) {
    __shared__ float s_in[4096];
    int n = blockIdx.x, t = blockIdx.y;
    const float* pin = in + (size_t)t * 32768 + n * 4096;
    int tid = threadIdx.x;                       // 320
    for (int i = tid; i < 4096; i += 320) s_in[i] = pin[i];
    __syncthreads();
    int o = tid >> 5, lane = tid & 31;
    const float* pw = wfc + o * 4096;
    float acc = 0.f;
    #pragma unroll 4
    for (int i = lane; i < 4096; i += 32) acc = fmaf(pw[i], s_in[i], acc);
    #pragma unroll
    for (int off = 16; off; off >>= 1) acc += __shfl_down_sync(0xffffffffu, acc, off);
    if (lane == 0) out[(size_t)t * 80 + n * 10 + o] = acc;
}

// ---------------- final spike scan -> T-minor d_out ----------------
__global__ void spike_tm_out(const float* __restrict__ u, float* __restrict__ out, int M) {
    int m = blockIdx.x * blockDim.x + threadIdx.x;
    if (m >= M) return;
    float ref[KREF], buf[KREF];
    #pragma unroll
    for (int k = 0; k < KREF; k++) { ref[k] = g_REF[k]; buf[k] = 0.f; }
    for (int t = 0; t < T; t++) {
        float ueff = u[(size_t)t * M + m] + buf[0];
        float s = (ueff >= 10.0f) ? 1.0f : 0.0f;
        if (s != 0.f) {
            #pragma unroll
            for (int k = 1; k < KREF; k++) buf[k] += ref[k];
        }
        #pragma unroll
        for (int k = 0; k < KREF - 1; k++) buf[k] = buf[k + 1];
        buf[KREF - 1] = 0.f;
        out[(size_t)m * T + t] = s;
    }
}

// ---------------- launch ----------------
extern "C" void kernel_launch(void* const* d_in, const int* in_sizes, int n_in,
                              void* d_out, int out_size) {
    const float* x   = (const float*)d_in[0];
    const float* w1  = (const float*)d_in[1];
    const float* w2  = (const float*)d_in[2];
    const float* w3  = (const float*)d_in[3];
    const float* wfc = (const float*)d_in[4];
    float* out = (float*)d_out;

    void *pY, *pX, *pZ;
    cudaGetSymbolAddress(&pY, g_bufY);
    cudaGetSymbolAddress(&pX, g_bufX);
    cudaGetSymbolAddress(&pZ, g_bufZ);
    float* Y = (float*)pY;
    float* X = (float*)pX;
    float* Z = (float*)pZ;

    init_filters<<<1, 128>>>();

    auto psp = [&](const float* i, float* o, int M) {
        // edge blocks (t0 = 0..70) need t<0 predicates; interior (t0 >= 80) does not
        psp_t<false><<<dim3((M + 255) / 256, 8), 256>>>(i, o, M, 0);
        psp_t<true ><<<dim3((M + 255) / 256, T / JT - 8), 256>>>(i, o, M, 8);
    };

    // ---- input transpose: (18496, 300) -> (300, 18496) ----
    transpose_k<<<dim3((T + 31) / 32, (18496 + 31) / 32), dim3(32, 8)>>>(x, Z, 18496, T);

    // ---- layer 1: s1 = spike(conv5x5(psp(x))) ----
    psp(Z, X, 18496);
    conv_t<2, 5, 1, 34, 34, 32, 32, 16, 4, 4, 4>
        <<<dim3(4, 8, T), dim3(256, 1)>>>(X, w1, Y, 18496, 131072);
    spike_tm<<<512, 256>>>(Y, 131072);

    // ---- layer 2: s2 = spike(psp(pool2(s1))) ----
    {
        int total = T * 32768;
        pool_tm<<<(total + 255) / 256, 256>>>(Y, X, 131072, 32768, 32, 32, total);
        psp(X, Z, 32768);
        spike_tm<<<128, 256>>>(Z, 32768);
    }
    // ---- layer 3: s3 = spike(conv3x3(psp(s2))) ----
    psp(Z, X, 32768);
    conv_t<16, 3, 1, 16, 16, 16, 16, 32, 16, 4, 4>
        <<<dim3(2, 8, T), dim3(64, 4)>>>(X, w2, Y, 32768, 65536);
    spike_tm<<<256, 256>>>(Y, 65536);

    // ---- layer 4: s4 = spike(psp(pool2(s3))) ----
    {
        int total = T * 16384;
        pool_tm<<<(total + 255) / 256, 256>>>(Y, X, 65536, 16384, 16, 16, total);
        psp(X, Z, 16384);
        spike_tm<<<64, 256>>>(Z, 16384);
    }
    // ---- layer 5: s5 = spike(conv3x3(psp(s4))) ----
    psp(Z, X, 16384);
    conv_t<32, 3, 1, 8, 8, 8, 8, 64, 64, 4, 4>
        <<<dim3(1, 8, T), dim3(16, 16)>>>(X, w3, Y, 16384, 32768);
    spike_tm<<<128, 256>>>(Y, 32768);

    // ---- output: spike(dense(psp(s5))) ----
    psp(Y, X, 32768);
    dense_t<<<dim3(8, T), 320>>>(X, wfc, Z);
    spike_tm_out<<<1, 128>>>(Z, out, 80);
}

// round 4
// speedup vs baseline: 6.6924x; 1.1652x over previous
#include <cuda_runtime.h>
#include <math.h>

static constexpr int T    = 300;
static constexpr int KSRM = 77;
static constexpr int KREF = 11;
static constexpr int JT   = 20;   // psp outputs per thread (T % JT == 0)

// ---------------- device-global scratch ----------------
__device__ float g_SRM[KSRM];
__device__ float g_REF[KREF];
__device__ float g_bufY[39321600];   // 131072*300
__device__ float g_bufX[9830400];
__device__ float g_bufZ[9830400];

__global__ void init_filters() {
    int i = threadIdx.x;
    if (i < KSRM) g_SRM[i] = (float)((double)i / 10.0 * exp(1.0 - (double)i / 10.0));
    if (i < KREF) g_REF[i] = (float)(-20.0 * (double)i * exp(1.0 - (double)i));
}

// ---------------- transpose (R,C) -> (C,R) ----------------
__global__ void transpose_k(const float* __restrict__ in, float* __restrict__ out,
                            int R, int C) {
    __shared__ float tile[32][33];
    int cb = blockIdx.x * 32, rb = blockIdx.y * 32;
    #pragma unroll
    for (int j = 0; j < 32; j += 8) {
        int r = rb + threadIdx.y + j, c = cb + threadIdx.x;
        tile[threadIdx.y + j][threadIdx.x] = (r < R && c < C) ? in[(size_t)r * C + c] : 0.f;
    }
    __syncthreads();
    #pragma unroll
    for (int j = 0; j < 32; j += 8) {
        int r = rb + threadIdx.x, c = cb + threadIdx.y + j;
        if (c < C && r < R) out[(size_t)c * R + r] = tile[threadIdx.x][threadIdx.y + j];
    }
}

// ---------------- psp: 77-tap causal FIR, circular register window, JT=20 ----------------
template<bool INTERIOR>
__global__ void psp_t(const float* __restrict__ in, float* __restrict__ out,
                      int M, int ybase) {
    __shared__ float ssrm[KSRM];
    for (int i = threadIdx.x; i < KSRM; i += blockDim.x) ssrm[i] = g_SRM[i];
    __syncthreads();

    int m = blockIdx.x * blockDim.x + threadIdx.x;
    if (m >= M) return;
    int t0 = (blockIdx.y + ybase) * JT;
    const float* pm = in + m;

    float acc[JT];
    float xv[JT];
    #pragma unroll
    for (int j = 0; j < JT; j++) acc[j] = 0.f;
    #pragma unroll
    for (int j = 0; j < JT; j++) {
        int ti = t0 + j - 1;
        int slot = ((j - 1) % JT + JT) % JT;
        xv[slot] = (INTERIOR || ti >= 0) ? __ldg(&pm[(size_t)ti * M]) : 0.f;
    }
    #pragma unroll
    for (int s = 1; s < KSRM; s++) {
        float wt = ssrm[s];
        #pragma unroll
        for (int j = 0; j < JT; j++) {
            int slot = (((j - s) % JT) + JT) % JT;
            acc[j] = fmaf(wt, xv[slot], acc[j]);
        }
        if (s < KSRM - 1) {
            int ti = t0 - s - 1;
            int slot = (((-s - 1) % JT) + JT) % JT;
            xv[slot] = (INTERIOR || ti >= 0) ? __ldg(&pm[(size_t)ti * M]) : 0.f;
        }
    }
    #pragma unroll
    for (int j = 0; j < JT; j++) out[(size_t)(t0 + j) * M + m] = acc[j];
}

// ---------------- templated conv, smem input tile + smem weights ----------------
// block: x = (WOUT/WV)*HOUT position threads, y = OBLK/OV. grid: (COUT/OBLK, N, T)
template<int CIN, int K, int PAD, int HIN, int WIN, int HOUT, int WOUT,
         int COUT, int OBLK, int OV, int WV>
__global__ void conv_t(const float* __restrict__ in, const float* __restrict__ wgt,
                       float* __restrict__ out, int Min, int Mout) {
    constexpr int CKK  = CIN * K * K;
    constexpr int WTHR = WOUT / WV;
    constexpr int TILE = CIN * HIN * WIN;
    __shared__ float s_in[TILE];
    __shared__ float s_w[OBLK * CKK];

    int t = blockIdx.z, n = blockIdx.y;
    int oblk0 = blockIdx.x * OBLK;
    const float* inb = in + (size_t)t * Min + (size_t)n * TILE;
    int nth = blockDim.x * blockDim.y;
    int tid = threadIdx.y * blockDim.x + threadIdx.x;
    for (int i = tid; i < TILE; i += nth) s_in[i] = inb[i];
    const float* wb = wgt + (size_t)oblk0 * CKK;
    for (int i = tid; i < OBLK * CKK; i += nth) s_w[i] = wb[i];
    __syncthreads();

    int w0 = (threadIdx.x % WTHR) * WV;
    int h  = threadIdx.x / WTHR;
    int oo = threadIdx.y * OV;

    float acc[OV][WV];
    #pragma unroll
    for (int o = 0; o < OV; o++)
        #pragma unroll
        for (int v = 0; v < WV; v++) acc[o][v] = 0.f;

    #pragma unroll 4
    for (int c = 0; c < CIN; c++) {
        #pragma unroll
        for (int kh = 0; kh < K; kh++) {
            int ih = h + kh - PAD;
            bool okh = (ih >= 0 && ih < HIN);
            float win[WV + K - 1];
            #pragma unroll
            for (int j = 0; j < WV + K - 1; j++) {
                int iw = w0 + j - PAD;
                win[j] = (okh && iw >= 0 && iw < WIN)
                       ? s_in[(c * HIN + ih) * WIN + iw] : 0.f;
            }
            #pragma unroll
            for (int kw = 0; kw < K; kw++) {
                #pragma unroll
                for (int o = 0; o < OV; o++) {
                    float wv = s_w[(oo + o) * CKK + (c * K + kh) * K + kw];
                    #pragma unroll
                    for (int v = 0; v < WV; v++)
                        acc[o][v] = fmaf(wv, win[kw + v], acc[o][v]);
                }
            }
        }
    }
    size_t ob = (size_t)t * Mout + (((size_t)n * COUT + oblk0 + oo) * HOUT + h) * WOUT + w0;
    #pragma unroll
    for (int o = 0; o < OV; o++)
        #pragma unroll
        for (int v = 0; v < WV; v++)
            out[ob + (size_t)o * (HOUT * WOUT) + v] = acc[o][v];
}

// ---------------- refractory LUT builder (oldest-first add order == reference) ----------------
__device__ __forceinline__ void build_lut(float* lut) {
    int nth = blockDim.x * blockDim.y;
    int tid = threadIdx.y * blockDim.x + threadIdx.x;
    for (int e = tid; e < 1024; e += nth) {
        float a = 0.f;
        #pragma unroll
        for (int i = 9; i >= 0; i--)
            if ((e >> i) & 1) a += g_REF[i + 1];
        lut[e] = a;
    }
    __syncthreads();
}

// ---------------- fused spike + 2x2 pool (time-major) ----------------
template<int HI, int WI>
__global__ void spikepool_lut(const float* __restrict__ u, float* __restrict__ out, int Mo) {
    __shared__ float lut[1024];
    build_lut(lut);
    int mo = blockIdx.x * blockDim.x + threadIdx.x;
    if (mo >= Mo) return;
    constexpr int WO = WI / 2, HO = HI / 2;
    int w = mo % WO; int r = mo / WO;
    int h = r % HO;  int nc = r / HO;
    int Mi = Mo * 4;
    const float* p = u + ((size_t)nc * HI + 2 * h) * WI + 2 * w;
    unsigned m0 = 0, m1 = 0, m2 = 0, m3 = 0;
    for (int t = 0; t < T; t++) {
        const float* pt = p + (size_t)t * Mi;
        float u0 = pt[0]      + lut[m0];
        float u1 = pt[1]      + lut[m1];
        float u2 = pt[WI]     + lut[m2];
        float u3 = pt[WI + 1] + lut[m3];
        bool b0 = u0 >= 10.f, b1 = u1 >= 10.f, b2 = u2 >= 10.f, b3 = u3 >= 10.f;
        float s0 = b0 ? 1.f : 0.f, s1 = b1 ? 1.f : 0.f;
        float s2 = b2 ? 1.f : 0.f, s3 = b3 ? 1.f : 0.f;
        m0 = ((m0 << 1) | (unsigned)b0) & 1023u;
        m1 = ((m1 << 1) | (unsigned)b1) & 1023u;
        m2 = ((m2 << 1) | (unsigned)b2) & 1023u;
        m3 = ((m3 << 1) | (unsigned)b3) & 1023u;
        out[(size_t)t * Mo + mo] = 2.75f * ((s0 + s1) + (s2 + s3));
    }
}

// ---------------- spike scan via LUT, in-place, time-major ----------------
__global__ void spike_lut(float* __restrict__ u, int M) {
    __shared__ float lut[1024];
    build_lut(lut);
    int m = blockIdx.x * blockDim.x + threadIdx.x;
    if (m >= M) return;
    unsigned mask = 0;
    for (int t = 0; t < T; t++) {
        float ueff = u[(size_t)t * M + m] + lut[mask];
        bool b = ueff >= 10.f;
        u[(size_t)t * M + m] = b ? 1.f : 0.f;
        mask = ((mask << 1) | (unsigned)b) & 1023u;
    }
}

// ---------------- final spike scan -> T-minor d_out ----------------
__global__ void spike_lut_out(const float* __restrict__ u, float* __restrict__ out, int M) {
    __shared__ float lut[1024];
    build_lut(lut);
    int m = blockIdx.x * blockDim.x + threadIdx.x;
    if (m >= M) return;
    unsigned mask = 0;
    for (int t = 0; t < T; t++) {
        float ueff = u[(size_t)t * M + m] + lut[mask];
        bool b = ueff >= 10.f;
        out[(size_t)m * T + t] = b ? 1.f : 0.f;
        mask = ((mask << 1) | (unsigned)b) & 1023u;
    }
}

// ---------------- dense: block per (n, 20-t group), warp per output ----------------
__global__ void dense_w(const float* __restrict__ in, const float* __restrict__ wfc,
                        float* __restrict__ out) {
    __shared__ float s_in[4096];
    int n = blockIdx.x, tg = blockIdx.y;
    int tid = threadIdx.x;                 // 320
    int o = tid >> 5, lane = tid & 31;
    const float* pw = wfc + o * 4096;
    for (int k = 0; k < 20; k++) {
        int t = tg * 20 + k;
        const float* pin = in + (size_t)t * 32768 + n * 4096;
        __syncthreads();
        for (int i = tid; i < 4096; i += 320) s_in[i] = pin[i];
        __syncthreads();
        float acc = 0.f;
        #pragma unroll 4
        for (int i = lane; i < 4096; i += 32) acc = fmaf(pw[i], s_in[i], acc);
        #pragma unroll
        for (int off = 16; off; off >>= 1) acc += __shfl_down_sync(0xffffffffu, acc, off);
        if (lane == 0) out[(size_t)t * 80 + n * 10 + o] = acc;
    }
}

// ---------------- launch ----------------
extern "C" void kernel_launch(void* const* d_in, const int* in_sizes, int n_in,
                              void* d_out, int out_size) {
    const float* x   = (const float*)d_in[0];
    const float* w1  = (const float*)d_in[1];
    const float* w2  = (const float*)d_in[2];
    const float* w3  = (const float*)d_in[3];
    const float* wfc = (const float*)d_in[4];
    float* out = (float*)d_out;

    void *pY, *pX, *pZ;
    cudaGetSymbolAddress(&pY, g_bufY);
    cudaGetSymbolAddress(&pX, g_bufX);
    cudaGetSymbolAddress(&pZ, g_bufZ);
    float* Y = (float*)pY;
    float* X = (float*)pX;
    float* Z = (float*)pZ;

    init_filters<<<1, 128>>>();

    auto psp = [&](const float* i, float* o, int M) {
        // edge blocks t0 in {0,20,40,60}; interior t0 >= 80 (t0-76 >= 0)
        psp_t<false><<<dim3((M + 255) / 256, 4), 256>>>(i, o, M, 0);
        psp_t<true ><<<dim3((M + 255) / 256, T / JT - 4), 256>>>(i, o, M, 4);
    };

    // ---- input transpose: (18496, 300) -> (300, 18496) ----
    transpose_k<<<dim3((T + 31) / 32, (18496 + 31) / 32), dim3(32, 8)>>>(x, Z, 18496, T);

    // ---- layer 1+2 front: u1 = conv5x5(psp(x)); pooled = spikepool(u1) ----
    psp(Z, X, 18496);
    conv_t<2, 5, 1, 34, 34, 32, 32, 16, 16, 4, 4>
        <<<dim3(1, 8, T), dim3(256, 4)>>>(X, w1, Y, 18496, 131072);
    spikepool_lut<32, 32><<<128, 256>>>(Y, X, 32768);

    // ---- layer 2 tail + layer 3: s2 = spike(psp(pooled)); u3 = conv3x3(psp(s2)) ----
    psp(X, Z, 32768);
    spike_lut<<<128, 256>>>(Z, 32768);
    psp(Z, X, 32768);
    conv_t<16, 3, 1, 16, 16, 16, 16, 32, 32, 4, 4>
        <<<dim3(1, 8, T), dim3(64, 8)>>>(X, w2, Y, 32768, 65536);
    spikepool_lut<16, 16><<<64, 256>>>(Y, X, 16384);

    // ---- layer 4 tail + layer 5 ----
    psp(X, Z, 16384);
    spike_lut<<<64, 256>>>(Z, 16384);
    psp(Z, X, 16384);
    conv_t<32, 3, 1, 8, 8, 8, 8, 64, 32, 4, 4>
        <<<dim3(2, 8, T), dim3(16, 8)>>>(X, w3, Y, 16384, 32768);
    spike_lut<<<128, 256>>>(Y, 32768);

    // ---- output: spike(dense(psp(s5))) ----
    psp(Y, X, 32768);
    dense_w<<<dim3(8, 15), 320>>>(X, wfc, Z);
    spike_lut_out<<<1, 128>>>(Z, out, 80);
}